// round 3
// baseline (speedup 1.0000x reference)
#include <cuda_runtime.h>
#include <cuda_bf16.h>

#define NN 8192
#define EE 131072
#define IS3 0.5773502691896258f

// ---------------- static scratch (no allocations) ----------------
__device__ float g_US[NN*128];
__device__ float g_UV[NN*384];
__device__ float g_SRC[NN*128];
__device__ float g_TGT[NN*128];
__device__ float g_AS[NN*64];
__device__ float g_AT[NN*64];
__device__ float g_BS[NN*64];
__device__ float g_BT[NN*64];
__device__ float g_T0[EE*64];
__device__ float g_T0D[EE*64];
__device__ float g_HA[EE*64];
__device__ float g_HB[EE*64];
__device__ float g_TPW[(size_t)EE*512];
__device__ float g_ED[EE];
__device__ float g_MSGS[NN*256];
__device__ float g_MSGV[NN*768];
__device__ float g_DENS[NN];
__device__ float g_INVD[NN];
__device__ float g_MS[NN*256];
__device__ float g_MV[NN*384];
__device__ float g_OS[NN*128];
__device__ float g_OV[NN*384];
__device__ int   g_CNT[NN];
__device__ int   g_OFF[NN+1];
__device__ int   g_CUR[NN];
__device__ int   g_BKT[EE];

// ---------------- generic strided GEMM ----------------
// Y[r, c] (at Y[r*ldy + c*sy]) = scale * (row_scale? row_scale[r] : 1) *
//                                sum_m X[r*ldx + m*sx] * W[m*wld + c]
// grid = (cols/64, rows/64), 256 threads. rows, cols multiples of 64. K arbitrary.
__global__ void __launch_bounds__(256) gemm_kernel(
    const float* __restrict__ X, int ldx, int sx,
    const float* __restrict__ W, int wld,
    float* __restrict__ Y, int ldy, int sy,
    int K, float scale,
    const float* __restrict__ row_scale, int accumulate)
{
    __shared__ __align__(16) float Xs[16][68];
    __shared__ __align__(16) float Ws[16][64];

    int t  = threadIdx.x;
    int r0 = blockIdx.y * 64;
    int c0 = blockIdx.x * 64;
    int tr = t >> 4, tc = t & 15;

    float acc[4][4] = {};

    for (int m0 = 0; m0 < K; m0 += 16) {
        #pragma unroll
        for (int i = 0; i < 4; i++) {
            int idx = t + i * 256;
            int mkx = idx & 15, rr = idx >> 4;
            int mx = m0 + mkx;
            Xs[mkx][rr] = (mx < K) ? X[(size_t)(r0 + rr) * ldx + (size_t)mx * sx] : 0.f;
            int cc = idx & 63, mkw = idx >> 6;
            int mw = m0 + mkw;
            Ws[mkw][cc] = (mw < K) ? W[(size_t)mw * wld + c0 + cc] : 0.f;
        }
        __syncthreads();
        #pragma unroll
        for (int mk = 0; mk < 16; mk++) {
            float4 xv = *reinterpret_cast<const float4*>(&Xs[mk][tr * 4]);
            float4 wv = *reinterpret_cast<const float4*>(&Ws[mk][tc * 4]);
            float xr[4] = {xv.x, xv.y, xv.z, xv.w};
            float wr[4] = {wv.x, wv.y, wv.z, wv.w};
            #pragma unroll
            for (int a = 0; a < 4; a++)
                #pragma unroll
                for (int b = 0; b < 4; b++)
                    acc[a][b] = fmaf(xr[a], wr[b], acc[a][b]);
        }
        __syncthreads();
    }

    #pragma unroll
    for (int a = 0; a < 4; a++) {
        int row = r0 + tr * 4 + a;
        float rs = scale;
        if (row_scale) rs *= row_scale[row];
        #pragma unroll
        for (int b = 0; b < 4; b++) {
            int col = c0 + tc * 4 + b;
            size_t idx = (size_t)row * ldy + (size_t)col * sy;
            float v = acc[a][b] * rs;
            if (accumulate) Y[idx] += v; else Y[idx] = v;
        }
    }
}

// ---------------- bucketing ----------------
__global__ void zero_cnt_kernel() {
    int i = blockIdx.x * blockDim.x + threadIdx.x;
    if (i < NN) g_CNT[i] = 0;
}

__global__ void count_kernel(const int* __restrict__ ei) {
    int e = blockIdx.x * blockDim.x + threadIdx.x;
    if (e < EE) atomicAdd(&g_CNT[ei[EE + e]], 1);
}

__global__ void __launch_bounds__(1024) scan_kernel() {
    __shared__ int sums[1024];
    int t = threadIdx.x;
    int base = t * 8;
    int local[8];
    int s = 0;
    #pragma unroll
    for (int i = 0; i < 8; i++) { local[i] = g_CNT[base + i]; s += local[i]; }
    sums[t] = s;
    __syncthreads();
    for (int d = 1; d < 1024; d <<= 1) {
        int v = (t >= d) ? sums[t - d] : 0;
        __syncthreads();
        sums[t] += v;
        __syncthreads();
    }
    int run = (t == 0) ? 0 : sums[t - 1];
    #pragma unroll
    for (int i = 0; i < 8; i++) { g_OFF[base + i] = run; g_CUR[base + i] = run; run += local[i]; }
    if (t == 1023) g_OFF[NN] = run;
}

__global__ void fill_kernel(const int* __restrict__ ei) {
    int e = blockIdx.x * blockDim.x + threadIdx.x;
    if (e < EE) {
        int pos = atomicAdd(&g_CUR[ei[EE + e]], 1);
        g_BKT[pos] = e;
    }
}

__global__ void sort_kernel() {
    int n = blockIdx.x * blockDim.x + threadIdx.x;
    if (n >= NN) return;
    int s = g_OFF[n], t = g_OFF[n + 1];
    for (int i = s + 1; i < t; i++) {
        int v = g_BKT[i];
        int j = i - 1;
        while (j >= s && g_BKT[j] > v) { g_BKT[j + 1] = g_BKT[j]; j--; }
        g_BKT[j + 1] = v;
    }
}

// ---------------- edge pre (h0 + density) ----------------
// 4 edges per 256-thread block; thread j (0..63) = channel j of edge slot s.
__global__ void __launch_bounds__(256) edge_pre_kernel(
    const int* __restrict__ ei, const float* __restrict__ Wd1)
{
    __shared__ float red[4][64];
    const float rs264 = 0.061545745489666336f;  // 1/sqrt(264)
    int t = threadIdx.x;
    int s = t >> 6, j = t & 63;
    int e = blockIdx.x * 4 + s;
    int snd = ei[e], rcv = ei[EE + e];

    float h0 = (g_T0[e * 64 + j] + g_AS[snd * 64 + j] + g_AT[rcv * 64 + j]) * rs264;
    h0 = h0 / (1.f + __expf(-h0));
    g_HA[e * 64 + j] = h0;

    float d0 = (g_T0D[e * 64 + j] + g_BS[snd * 64 + j] + g_BT[rcv * 64 + j]) * rs264;
    d0 = d0 / (1.f + __expf(-d0));
    red[s][j] = d0 * Wd1[j];
    __syncthreads();
    for (int o = 32; o > 0; o >>= 1) {
        if (j < o) red[s][j] += red[s][j + o];
        __syncthreads();
    }
    if (j == 0) {
        float x = red[s][0] * 0.125f;
        g_ED[e] = tanhf(x * x);
    }
}

__global__ void silu_kernel(float* __restrict__ p, int n) {
    int i = blockIdx.x * blockDim.x + threadIdx.x;
    if (i < n) { float x = p[i]; p[i] = x / (1.f + __expf(-x)); }
}

// ---------------- per-node message gather (atomic-free segment sum) ----------------
__global__ void __launch_bounds__(256) gather_kernel(
    const int* __restrict__ ei, const float* __restrict__ edge_attrs)
{
    int n = blockIdx.x;
    int j = threadIdx.x;
    int s = g_OFF[n], t = g_OFF[n + 1];
    float as = 0.f, av0 = 0.f, av1 = 0.f, av2 = 0.f, dens = 0.f;

    for (int i = s; i < t; i++) {
        int e = g_BKT[i];
        int snd = ei[e];
        float y0  = __ldg(&edge_attrs[e * 4 + 0]);
        float y10 = __ldg(&edge_attrs[e * 4 + 1]);
        float y11 = __ldg(&edge_attrs[e * 4 + 2]);
        float y12 = __ldg(&edge_attrs[e * 4 + 3]);
        const float* tp = g_TPW + (size_t)e * 512;
        if (j < 128) {
            float w1 = tp[j], w2 = tp[128 + j];
            float xs = g_US[snd * 128 + j];
            as = fmaf(w1 * xs, y0, as);
            float t2 = w2 * xs * IS3;
            av0 = fmaf(t2, y10, av0);
            av1 = fmaf(t2, y11, av1);
            av2 = fmaf(t2, y12, av2);
        } else {
            int u = j - 128;
            float w3 = tp[256 + u], w4 = tp[384 + u];
            const float* xv = g_UV + snd * 384 + u * 3;
            float x0 = xv[0], x1 = xv[1], x2 = xv[2];
            float sv = x0 * y10 + x1 * y11 + x2 * y12;
            as = fmaf(w4 * IS3, sv, as);
            float t3 = w3 * y0 * IS3;
            av0 = fmaf(t3, x0, av0);
            av1 = fmaf(t3, x1, av1);
            av2 = fmaf(t3, x2, av2);
        }
        if (j == 0) dens += g_ED[e];
    }
    g_MSGS[n * 256 + j] = as;
    g_MSGV[n * 768 + j * 3 + 0] = av0;
    g_MSGV[n * 768 + j * 3 + 1] = av1;
    g_MSGV[n * 768 + j * 3 + 2] = av2;
    if (j == 0) g_DENS[n] = dens;
}

__global__ void invd_kernel(const float* __restrict__ alpha, const float* __restrict__ beta) {
    int n = blockIdx.x * blockDim.x + threadIdx.x;
    if (n < NN) g_INVD[n] = 1.f / (g_DENS[n] * beta[0] + alpha[0]);
}

// out_s = silu(m_s[:,:128]); out_v = m_v * sigmoid(m_s[:,128:])
__global__ void act_kernel() {
    int idx = blockIdx.x * blockDim.x + threadIdx.x;
    int n = idx >> 7, u = idx & 127;
    float ms = g_MS[n * 256 + u];
    g_OS[n * 128 + u] = ms / (1.f + __expf(-ms));
    float sg = 1.f / (1.f + __expf(-g_MS[n * 256 + 128 + u]));
    int b = n * 384 + u * 3;
    g_OV[b + 0] = g_MV[b + 0] * sg;
    g_OV[b + 1] = g_MV[b + 1] * sg;
    g_OV[b + 2] = g_MV[b + 2] * sg;
}

// ---------------- host ----------------
static float* sym(const void* symbol) {
    void* p = nullptr;
    cudaGetSymbolAddress(&p, symbol);
    return (float*)p;
}

extern "C" void kernel_launch(void* const* d_in, const int* in_sizes, int n_in,
                              void* d_out, int out_size)
{
    const float* node_attrs = (const float*)d_in[0];
    const float* node_feats = (const float*)d_in[1];
    const float* edge_attrs = (const float*)d_in[2];
    const float* edge_feats = (const float*)d_in[3];
    const int*   ei         = (const int*)  d_in[4];
    const float* W_skip_s = (const float*)d_in[5];
    const float* W_skip_v = (const float*)d_in[6];
    const float* W_up_s   = (const float*)d_in[7];
    const float* W_up_v   = (const float*)d_in[8];
    const float* W_src    = (const float*)d_in[9];
    const float* W_tgt    = (const float*)d_in[10];
    const float* W_r0     = (const float*)d_in[11];
    const float* W_r1     = (const float*)d_in[12];
    const float* W_r2     = (const float*)d_in[13];
    const float* W_r3     = (const float*)d_in[14];
    const float* W_d0     = (const float*)d_in[15];
    const float* W_d1     = (const float*)d_in[16];
    const float* W1_s     = (const float*)d_in[17];
    const float* W1_v     = (const float*)d_in[18];
    const float* Wres_s   = (const float*)d_in[19];
    const float* Wres_v   = (const float*)d_in[20];
    const float* W2_s     = (const float*)d_in[21];
    const float* W2_v     = (const float*)d_in[22];
    const float* alpha    = (const float*)d_in[23];
    const float* beta     = (const float*)d_in[24];

    float* out    = (float*)d_out;            // (N,128,4) flattened
    float* out_sc = (float*)d_out + (size_t)NN * 512;  // (N,512)

    float* US  = sym(g_US);   float* UV  = sym(g_UV);
    float* SRC = sym(g_SRC);  float* TGT = sym(g_TGT);
    float* AS  = sym(g_AS);   float* AT  = sym(g_AT);
    float* BS  = sym(g_BS);   float* BT  = sym(g_BT);
    float* T0  = sym(g_T0);   float* T0D = sym(g_T0D);
    float* HA  = sym(g_HA);   float* HB  = sym(g_HB);
    float* TPW = sym(g_TPW);
    float* MSGS = sym(g_MSGS); float* MSGV = sym(g_MSGV);
    float* INVD = sym(g_INVD);
    float* MS  = sym(g_MS);   float* MV  = sym(g_MV);
    float* OS  = sym(g_OS);   float* OV  = sym(g_OV);

    const float rs128 = 0.08838834764831845f;   // 1/sqrt(128)
    const float rs10  = 0.31622776601683794f;   // 1/sqrt(10)
    const float rs64  = 0.125f;                 // 1/sqrt(64)
    const float rs256 = 0.0625f;                // 1/sqrt(256)

    dim3 B(256);
    int NR = NN / 64;     // 128 row-blocks for node GEMMs
    int ER = EE / 64;     // 2048 row-blocks for edge GEMMs

    // --- Phase A: node precompute ---
    // sc (skip path) -> second half of output
    gemm_kernel<<<dim3(2, NR), B>>>(node_feats, 512, 1, W_skip_s, 128, out_sc, 512, 1, 128, rs128, nullptr, 0);
    for (int c = 0; c < 3; c++)
        gemm_kernel<<<dim3(2, NR), B>>>(node_feats + 128 + c, 512, 3, W_skip_v, 128, out_sc + 128 + c, 512, 3, 128, rs128, nullptr, 0);
    // us, uv
    gemm_kernel<<<dim3(2, NR), B>>>(node_feats, 512, 1, W_up_s, 128, US, 128, 1, 128, rs128, nullptr, 0);
    for (int c = 0; c < 3; c++)
        gemm_kernel<<<dim3(2, NR), B>>>(node_feats + 128 + c, 512, 3, W_up_v, 128, UV + c, 384, 3, 128, rs128, nullptr, 0);
    // src_e, tgt_e
    gemm_kernel<<<dim3(2, NR), B>>>(node_attrs, 10, 1, W_src, 128, SRC, 128, 1, 10, rs10, nullptr, 0);
    gemm_kernel<<<dim3(2, NR), B>>>(node_attrs, 10, 1, W_tgt, 128, TGT, 128, 1, 10, rs10, nullptr, 0);
    // factored r0/d0 node parts
    gemm_kernel<<<dim3(1, NR), B>>>(SRC, 128, 1, W_r0 + 8 * 64,   64, AS, 64, 1, 128, 1.f, nullptr, 0);
    gemm_kernel<<<dim3(1, NR), B>>>(TGT, 128, 1, W_r0 + 136 * 64, 64, AT, 64, 1, 128, 1.f, nullptr, 0);
    gemm_kernel<<<dim3(1, NR), B>>>(SRC, 128, 1, W_d0 + 8 * 64,   64, BS, 64, 1, 128, 1.f, nullptr, 0);
    gemm_kernel<<<dim3(1, NR), B>>>(TGT, 128, 1, W_d0 + 136 * 64, 64, BT, 64, 1, 128, 1.f, nullptr, 0);
    // per-edge 8-dim parts
    gemm_kernel<<<dim3(1, ER), B>>>(edge_feats, 8, 1, W_r0, 64, T0,  64, 1, 8, 1.f, nullptr, 0);
    gemm_kernel<<<dim3(1, ER), B>>>(edge_feats, 8, 1, W_d0, 64, T0D, 64, 1, 8, 1.f, nullptr, 0);

    // --- bucketing for segment sums ---
    zero_cnt_kernel<<<NN / 256, B>>>();
    count_kernel<<<EE / 256, B>>>(ei);
    scan_kernel<<<1, 1024>>>();
    fill_kernel<<<EE / 256, B>>>(ei);
    sort_kernel<<<NN / 256, B>>>();

    // --- Phase B: edge MLP ---
    edge_pre_kernel<<<EE / 4, B>>>(ei, W_d1);
    gemm_kernel<<<dim3(1, ER), B>>>(HA, 64, 1, W_r1, 64, HB, 64, 1, 64, rs64, nullptr, 0);
    silu_kernel<<<EE * 64 / 256, B>>>(HB, EE * 64);
    gemm_kernel<<<dim3(1, ER), B>>>(HB, 64, 1, W_r2, 64, HA, 64, 1, 64, rs64, nullptr, 0);
    silu_kernel<<<EE * 64 / 256, B>>>(HA, EE * 64);
    gemm_kernel<<<dim3(8, ER), B>>>(HA, 64, 1, W_r3, 512, TPW, 512, 1, 64, rs64, nullptr, 0);

    // --- message aggregation ---
    gather_kernel<<<NN, B>>>(ei, edge_attrs);
    invd_kernel<<<NN / 256, B>>>(alpha, beta);

    // --- Phase C: node output ---
    gemm_kernel<<<dim3(4, NR), B>>>(MSGS, 256, 1, W1_s, 256, MS, 256, 1, 256, rs256, INVD, 0);
    gemm_kernel<<<dim3(4, NR), B>>>(US, 128, 1, Wres_s, 256, MS, 256, 1, 128, rs128, nullptr, 1);
    for (int c = 0; c < 3; c++) {
        gemm_kernel<<<dim3(2, NR), B>>>(MSGV + c, 768, 3, W1_v, 128, MV + c, 384, 3, 256, rs256, INVD, 0);
        gemm_kernel<<<dim3(2, NR), B>>>(UV + c, 384, 3, Wres_v, 128, MV + c, 384, 3, 128, rs128, nullptr, 1);
    }
    act_kernel<<<NN * 128 / 256, B>>>();
    // f_s -> out[:, :, 0] ; f_v[c] -> out[:, :, 1+c]
    gemm_kernel<<<dim3(2, NR), B>>>(OS, 128, 1, W2_s, 128, out, 512, 4, 128, rs128, nullptr, 0);
    for (int c = 0; c < 3; c++)
        gemm_kernel<<<dim3(2, NR), B>>>(OV + c, 384, 3, W2_v, 128, out + 1 + c, 512, 4, 128, rs128, nullptr, 0);
}

// round 4
// speedup vs baseline: 1.0834x; 1.0834x over previous
#include <cuda_runtime.h>
#include <cuda_bf16.h>
#include <cstdint>

#define NN 8192
#define EE 131072
#define IS3 0.5773502691896258f

// ---------------- static scratch (no allocations) ----------------
__device__ float g_US[NN*128];
__device__ float g_UV[NN*384];
__device__ float g_SRC[NN*128];
__device__ float g_TGT[NN*128];
__device__ float g_AS[NN*64];
__device__ float g_AT[NN*64];
__device__ float g_BS[NN*64];
__device__ float g_BT[NN*64];
__device__ float g_T0[EE*64];
__device__ float g_T0D[EE*64];
__device__ float g_HA[EE*64];
__device__ float g_HB[EE*64];
__device__ float g_TPW[(size_t)EE*512];
__device__ float g_ED[EE];
__device__ float g_MSGS[NN*256];
__device__ float g_MSGV[NN*768];
__device__ float g_DENS[NN];
__device__ float g_INVD[NN];
__device__ float g_MS[NN*256];
__device__ float g_MV[NN*384];
__device__ float g_OS[NN*128];
__device__ float g_OV[NN*384];
__device__ int   g_CNT[NN];
__device__ int   g_OFF[NN+1];
__device__ int   g_CUR[NN];
__device__ int   g_BKT[EE];

// ---------------- tf32 helpers ----------------
__device__ __forceinline__ uint32_t f2tf(float x) {
    uint32_t u;
    asm("cvt.rna.tf32.f32 %0, %1;" : "=r"(u) : "f"(x));
    return u;
}

__device__ __forceinline__ void mma_tf32(float* c, const uint32_t* a, uint32_t b0, uint32_t b1) {
    asm volatile(
        "mma.sync.aligned.m16n8k8.row.col.f32.tf32.tf32.f32 "
        "{%0,%1,%2,%3}, {%4,%5,%6,%7}, {%8,%9}, {%0,%1,%2,%3};"
        : "+f"(c[0]), "+f"(c[1]), "+f"(c[2]), "+f"(c[3])
        : "r"(a[0]), "r"(a[1]), "r"(a[2]), "r"(a[3]), "r"(b0), "r"(b1));
}

// ---------------- tensor-core strided GEMM ----------------
// Y[r, c] (at Y[r*ldy + c*sy]) = post( scale * (row_scale? rs[r]:1) *
//                                sum_m X[r*ldx + m*sx] * W[m*wld + c] )
// post: act==1 -> silu. accumulate: Y += v instead of Y = v.
// grid = (cols/64, rows/128), 256 threads. rows % 128 == 0, cols % 64 == 0. K arbitrary.
#define AP 68   // A smem pitch (banks (4g+l) conflict-free)
#define BP 72   // B smem pitch (banks (8l+g) conflict-free)
#define MMA_SMEM ((128*AP + 64*BP) * 4)

__global__ void __launch_bounds__(256) mma_gemm_kernel(
    const float* __restrict__ X, int ldx, int sx,
    const float* __restrict__ W, int wld,
    float* __restrict__ Y, int ldy, int sy,
    int K, float scale,
    const float* __restrict__ row_scale, int accumulate, int act)
{
    extern __shared__ uint32_t smem[];
    uint32_t* As = smem;            // [128][AP]
    uint32_t* Bs = smem + 128 * AP; // [64][BP]

    int t  = threadIdx.x;
    int r0 = blockIdx.y * 128;
    int c0 = blockIdx.x * 64;

    int warp = t >> 5, lane = t & 31;
    int wr = warp >> 1, wc = warp & 1;     // 4x2 warp grid, each 32 rows x 32 cols
    int g = lane >> 2, l = lane & 3;

    float acc[2][4][4] = {};

    for (int k0 = 0; k0 < K; k0 += 64) {
        // ---- stage X tile (128 x 64) ----
        bool vec = (sx == 1) && (K - k0 >= 64) && ((ldx & 3) == 0);
        if (vec) {
            #pragma unroll
            for (int i = 0; i < 8; i++) {
                int e = t + i * 256;           // 0..2047 float4 slots
                int row = e >> 4, c4 = (e & 15) * 4;
                float4 v = *reinterpret_cast<const float4*>(
                    &X[(size_t)(r0 + row) * ldx + k0 + c4]);
                uint4 u = make_uint4(f2tf(v.x), f2tf(v.y), f2tf(v.z), f2tf(v.w));
                *reinterpret_cast<uint4*>(&As[row * AP + c4]) = u;
            }
        } else {
            #pragma unroll
            for (int i = 0; i < 32; i++) {
                int e = t + i * 256;
                int row = e >> 6, col = e & 63;
                int kk = k0 + col;
                float x = (kk < K) ? X[(size_t)(r0 + row) * ldx + (size_t)kk * sx] : 0.f;
                As[row * AP + col] = f2tf(x);
            }
        }
        // ---- stage W tile (64 x 64) ----
        #pragma unroll
        for (int i = 0; i < 4; i++) {
            int e = t + i * 256;               // 0..1023 float4 slots
            int row = e >> 4, c4 = (e & 15) * 4;
            int kk = k0 + row;
            float4 v = make_float4(0.f, 0.f, 0.f, 0.f);
            if (kk < K)
                v = *reinterpret_cast<const float4*>(&W[(size_t)kk * wld + c0 + c4]);
            uint4 u = make_uint4(f2tf(v.x), f2tf(v.y), f2tf(v.z), f2tf(v.w));
            *reinterpret_cast<uint4*>(&Bs[row * BP + c4]) = u;
        }
        __syncthreads();

        // ---- 8 k-tiles of m16n8k8 ----
        #pragma unroll
        for (int kt = 0; kt < 8; kt++) {
            uint32_t a[2][4];
            #pragma unroll
            for (int mt = 0; mt < 2; mt++) {
                int base = (wr * 32 + mt * 16 + g) * AP + kt * 8 + l;
                a[mt][0] = As[base];
                a[mt][1] = As[base + 8 * AP];
                a[mt][2] = As[base + 4];
                a[mt][3] = As[base + 8 * AP + 4];
            }
            #pragma unroll
            for (int nt = 0; nt < 4; nt++) {
                int bcol = wc * 32 + nt * 8 + g;
                uint32_t b0 = Bs[(kt * 8 + l) * BP + bcol];
                uint32_t b1 = Bs[(kt * 8 + l + 4) * BP + bcol];
                mma_tf32(acc[0][nt], a[0], b0, b1);
                mma_tf32(acc[1][nt], a[1], b0, b1);
            }
        }
        __syncthreads();
    }

    // ---- epilogue ----
    #pragma unroll
    for (int mt = 0; mt < 2; mt++) {
        #pragma unroll
        for (int idx = 0; idx < 4; idx++) {
            int row = r0 + wr * 32 + mt * 16 + g + ((idx >= 2) ? 8 : 0);
            float rs = scale;
            if (row_scale) rs *= row_scale[row];
            #pragma unroll
            for (int nt = 0; nt < 4; nt++) {
                int col = c0 + wc * 32 + nt * 8 + 2 * l + (idx & 1);
                float v = acc[mt][nt][idx] * rs;
                if (act == 1) v = v / (1.f + __expf(-v));
                size_t o = (size_t)row * ldy + (size_t)col * sy;
                if (accumulate) Y[o] += v; else Y[o] = v;
            }
        }
    }
}

// ---------------- bucketing ----------------
__global__ void zero_cnt_kernel() {
    int i = blockIdx.x * blockDim.x + threadIdx.x;
    if (i < NN) g_CNT[i] = 0;
}

__global__ void count_kernel(const int* __restrict__ ei) {
    int e = blockIdx.x * blockDim.x + threadIdx.x;
    if (e < EE) atomicAdd(&g_CNT[ei[EE + e]], 1);
}

__global__ void __launch_bounds__(1024) scan_kernel() {
    __shared__ int sums[1024];
    int t = threadIdx.x;
    int base = t * 8;
    int local[8];
    int s = 0;
    #pragma unroll
    for (int i = 0; i < 8; i++) { local[i] = g_CNT[base + i]; s += local[i]; }
    sums[t] = s;
    __syncthreads();
    for (int d = 1; d < 1024; d <<= 1) {
        int v = (t >= d) ? sums[t - d] : 0;
        __syncthreads();
        sums[t] += v;
        __syncthreads();
    }
    int run = (t == 0) ? 0 : sums[t - 1];
    #pragma unroll
    for (int i = 0; i < 8; i++) { g_OFF[base + i] = run; g_CUR[base + i] = run; run += local[i]; }
    if (t == 1023) g_OFF[NN] = run;
}

__global__ void fill_kernel(const int* __restrict__ ei) {
    int e = blockIdx.x * blockDim.x + threadIdx.x;
    if (e < EE) {
        int pos = atomicAdd(&g_CUR[ei[EE + e]], 1);
        g_BKT[pos] = e;
    }
}

__global__ void sort_kernel() {
    int n = blockIdx.x * blockDim.x + threadIdx.x;
    if (n >= NN) return;
    int s = g_OFF[n], t = g_OFF[n + 1];
    for (int i = s + 1; i < t; i++) {
        int v = g_BKT[i];
        int j = i - 1;
        while (j >= s && g_BKT[j] > v) { g_BKT[j + 1] = g_BKT[j]; j--; }
        g_BKT[j + 1] = v;
    }
}

// ---------------- edge pre (h0 + density) ----------------
__global__ void __launch_bounds__(256) edge_pre_kernel(
    const int* __restrict__ ei, const float* __restrict__ Wd1)
{
    __shared__ float red[4][64];
    const float rs264 = 0.061545745489666336f;  // 1/sqrt(264)
    int t = threadIdx.x;
    int s = t >> 6, j = t & 63;
    int e = blockIdx.x * 4 + s;
    int snd = ei[e], rcv = ei[EE + e];

    float h0 = (g_T0[e * 64 + j] + g_AS[snd * 64 + j] + g_AT[rcv * 64 + j]) * rs264;
    h0 = h0 / (1.f + __expf(-h0));
    g_HA[e * 64 + j] = h0;

    float d0 = (g_T0D[e * 64 + j] + g_BS[snd * 64 + j] + g_BT[rcv * 64 + j]) * rs264;
    d0 = d0 / (1.f + __expf(-d0));
    red[s][j] = d0 * Wd1[j];
    __syncthreads();
    for (int o = 32; o > 0; o >>= 1) {
        if (j < o) red[s][j] += red[s][j + o];
        __syncthreads();
    }
    if (j == 0) {
        float x = red[s][0] * 0.125f;
        g_ED[e] = tanhf(x * x);
    }
}

// ---------------- per-node message gather (atomic-free segment sum) ----------------
__global__ void __launch_bounds__(256) gather_kernel(
    const int* __restrict__ ei, const float* __restrict__ edge_attrs)
{
    int n = blockIdx.x;
    int j = threadIdx.x;
    int s = g_OFF[n], t = g_OFF[n + 1];
    float as = 0.f, av0 = 0.f, av1 = 0.f, av2 = 0.f, dens = 0.f;

    for (int i = s; i < t; i++) {
        int e = g_BKT[i];
        int snd = ei[e];
        float y0  = __ldg(&edge_attrs[e * 4 + 0]);
        float y10 = __ldg(&edge_attrs[e * 4 + 1]);
        float y11 = __ldg(&edge_attrs[e * 4 + 2]);
        float y12 = __ldg(&edge_attrs[e * 4 + 3]);
        const float* tp = g_TPW + (size_t)e * 512;
        if (j < 128) {
            float w1 = tp[j], w2 = tp[128 + j];
            float xs = g_US[snd * 128 + j];
            as = fmaf(w1 * xs, y0, as);
            float t2 = w2 * xs * IS3;
            av0 = fmaf(t2, y10, av0);
            av1 = fmaf(t2, y11, av1);
            av2 = fmaf(t2, y12, av2);
        } else {
            int u = j - 128;
            float w3 = tp[256 + u], w4 = tp[384 + u];
            const float* xv = g_UV + snd * 384 + u * 3;
            float x0 = xv[0], x1 = xv[1], x2 = xv[2];
            float sv = x0 * y10 + x1 * y11 + x2 * y12;
            as = fmaf(w4 * IS3, sv, as);
            float t3 = w3 * y0 * IS3;
            av0 = fmaf(t3, x0, av0);
            av1 = fmaf(t3, x1, av1);
            av2 = fmaf(t3, x2, av2);
        }
        if (j == 0) dens += g_ED[e];
    }
    g_MSGS[n * 256 + j] = as;
    g_MSGV[n * 768 + j * 3 + 0] = av0;
    g_MSGV[n * 768 + j * 3 + 1] = av1;
    g_MSGV[n * 768 + j * 3 + 2] = av2;
    if (j == 0) g_DENS[n] = dens;
}

__global__ void invd_kernel(const float* __restrict__ alpha, const float* __restrict__ beta) {
    int n = blockIdx.x * blockDim.x + threadIdx.x;
    if (n < NN) g_INVD[n] = 1.f / (g_DENS[n] * beta[0] + alpha[0]);
}

// out_s = silu(m_s[:,:128]); out_v = m_v * sigmoid(m_s[:,128:])
__global__ void act_kernel() {
    int idx = blockIdx.x * blockDim.x + threadIdx.x;
    int n = idx >> 7, u = idx & 127;
    float ms = g_MS[n * 256 + u];
    g_OS[n * 128 + u] = ms / (1.f + __expf(-ms));
    float sg = 1.f / (1.f + __expf(-g_MS[n * 256 + 128 + u]));
    int b = n * 384 + u * 3;
    g_OV[b + 0] = g_MV[b + 0] * sg;
    g_OV[b + 1] = g_MV[b + 1] * sg;
    g_OV[b + 2] = g_MV[b + 2] * sg;
}

// ---------------- host ----------------
static float* sym(const void* symbol) {
    void* p = nullptr;
    cudaGetSymbolAddress(&p, symbol);
    return (float*)p;
}

extern "C" void kernel_launch(void* const* d_in, const int* in_sizes, int n_in,
                              void* d_out, int out_size)
{
    const float* node_attrs = (const float*)d_in[0];
    const float* node_feats = (const float*)d_in[1];
    const float* edge_attrs = (const float*)d_in[2];
    const float* edge_feats = (const float*)d_in[3];
    const int*   ei         = (const int*)  d_in[4];
    const float* W_skip_s = (const float*)d_in[5];
    const float* W_skip_v = (const float*)d_in[6];
    const float* W_up_s   = (const float*)d_in[7];
    const float* W_up_v   = (const float*)d_in[8];
    const float* W_src    = (const float*)d_in[9];
    const float* W_tgt    = (const float*)d_in[10];
    const float* W_r0     = (const float*)d_in[11];
    const float* W_r1     = (const float*)d_in[12];
    const float* W_r2     = (const float*)d_in[13];
    const float* W_r3     = (const float*)d_in[14];
    const float* W_d0     = (const float*)d_in[15];
    const float* W_d1     = (const float*)d_in[16];
    const float* W1_s     = (const float*)d_in[17];
    const float* W1_v     = (const float*)d_in[18];
    const float* Wres_s   = (const float*)d_in[19];
    const float* Wres_v   = (const float*)d_in[20];
    const float* W2_s     = (const float*)d_in[21];
    const float* W2_v     = (const float*)d_in[22];
    const float* alpha    = (const float*)d_in[23];
    const float* beta     = (const float*)d_in[24];

    float* out    = (float*)d_out;                      // (N,128,4) flattened
    float* out_sc = (float*)d_out + (size_t)NN * 512;   // (N,512)

    float* US  = sym(g_US);   float* UV  = sym(g_UV);
    float* SRC = sym(g_SRC);  float* TGT = sym(g_TGT);
    float* AS  = sym(g_AS);   float* AT  = sym(g_AT);
    float* BS  = sym(g_BS);   float* BT  = sym(g_BT);
    float* T0  = sym(g_T0);   float* T0D = sym(g_T0D);
    float* HA  = sym(g_HA);   float* HB  = sym(g_HB);
    float* TPW = sym(g_TPW);
    float* MSGS = sym(g_MSGS); float* MSGV = sym(g_MSGV);
    float* INVD = sym(g_INVD);
    float* MS  = sym(g_MS);   float* MV  = sym(g_MV);
    float* OS  = sym(g_OS);   float* OV  = sym(g_OV);

    const float rs128 = 0.08838834764831845f;   // 1/sqrt(128)
    const float rs10  = 0.31622776601683794f;   // 1/sqrt(10)
    const float rs64  = 0.125f;                 // 1/sqrt(64)
    const float rs256 = 0.0625f;                // 1/sqrt(256)

    cudaFuncSetAttribute(mma_gemm_kernel,
                         cudaFuncAttributeMaxDynamicSharedMemorySize, MMA_SMEM);

    dim3 B(256);
    int NR = NN / 128;    // 64 row-blocks for node GEMMs
    int ER = EE / 128;    // 1024 row-blocks for edge GEMMs
    size_t SH = MMA_SMEM;

    // --- Phase A: node precompute ---
    // sc (skip path) -> second half of output
    mma_gemm_kernel<<<dim3(2, NR), B, SH>>>(node_feats, 512, 1, W_skip_s, 128, out_sc, 512, 1, 128, rs128, nullptr, 0, 0);
    for (int c = 0; c < 3; c++)
        mma_gemm_kernel<<<dim3(2, NR), B, SH>>>(node_feats + 128 + c, 512, 3, W_skip_v, 128, out_sc + 128 + c, 512, 3, 128, rs128, nullptr, 0, 0);
    // us, uv
    mma_gemm_kernel<<<dim3(2, NR), B, SH>>>(node_feats, 512, 1, W_up_s, 128, US, 128, 1, 128, rs128, nullptr, 0, 0);
    for (int c = 0; c < 3; c++)
        mma_gemm_kernel<<<dim3(2, NR), B, SH>>>(node_feats + 128 + c, 512, 3, W_up_v, 128, UV + c, 384, 3, 128, rs128, nullptr, 0, 0);
    // src_e, tgt_e
    mma_gemm_kernel<<<dim3(2, NR), B, SH>>>(node_attrs, 10, 1, W_src, 128, SRC, 128, 1, 10, rs10, nullptr, 0, 0);
    mma_gemm_kernel<<<dim3(2, NR), B, SH>>>(node_attrs, 10, 1, W_tgt, 128, TGT, 128, 1, 10, rs10, nullptr, 0, 0);
    // factored r0/d0 node parts
    mma_gemm_kernel<<<dim3(1, NR), B, SH>>>(SRC, 128, 1, W_r0 + 8 * 64,   64, AS, 64, 1, 128, 1.f, nullptr, 0, 0);
    mma_gemm_kernel<<<dim3(1, NR), B, SH>>>(TGT, 128, 1, W_r0 + 136 * 64, 64, AT, 64, 1, 128, 1.f, nullptr, 0, 0);
    mma_gemm_kernel<<<dim3(1, NR), B, SH>>>(SRC, 128, 1, W_d0 + 8 * 64,   64, BS, 64, 1, 128, 1.f, nullptr, 0, 0);
    mma_gemm_kernel<<<dim3(1, NR), B, SH>>>(TGT, 128, 1, W_d0 + 136 * 64, 64, BT, 64, 1, 128, 1.f, nullptr, 0, 0);
    // per-edge 8-dim parts
    mma_gemm_kernel<<<dim3(1, ER), B, SH>>>(edge_feats, 8, 1, W_r0, 64, T0,  64, 1, 8, 1.f, nullptr, 0, 0);
    mma_gemm_kernel<<<dim3(1, ER), B, SH>>>(edge_feats, 8, 1, W_d0, 64, T0D, 64, 1, 8, 1.f, nullptr, 0, 0);

    // --- bucketing for segment sums ---
    zero_cnt_kernel<<<NN / 256, B>>>();
    count_kernel<<<EE / 256, B>>>(ei);
    scan_kernel<<<1, 1024>>>();
    fill_kernel<<<EE / 256, B>>>(ei);
    sort_kernel<<<NN / 256, B>>>();

    // --- Phase B: edge MLP (silu fused into GEMM epilogue) ---
    edge_pre_kernel<<<EE / 4, B>>>(ei, W_d1);
    mma_gemm_kernel<<<dim3(1, ER), B, SH>>>(HA, 64, 1, W_r1, 64, HB, 64, 1, 64, rs64, nullptr, 0, 1);
    mma_gemm_kernel<<<dim3(1, ER), B, SH>>>(HB, 64, 1, W_r2, 64, HA, 64, 1, 64, rs64, nullptr, 0, 1);
    mma_gemm_kernel<<<dim3(8, ER), B, SH>>>(HA, 64, 1, W_r3, 512, TPW, 512, 1, 64, rs64, nullptr, 0, 0);

    // --- message aggregation ---
    gather_kernel<<<NN, B>>>(ei, edge_attrs);
    invd_kernel<<<NN / 256, B>>>(alpha, beta);

    // --- Phase C: node output ---
    mma_gemm_kernel<<<dim3(4, NR), B, SH>>>(MSGS, 256, 1, W1_s, 256, MS, 256, 1, 256, rs256, INVD, 0, 0);
    mma_gemm_kernel<<<dim3(4, NR), B, SH>>>(US, 128, 1, Wres_s, 256, MS, 256, 1, 128, rs128, nullptr, 1, 0);
    for (int c = 0; c < 3; c++) {
        mma_gemm_kernel<<<dim3(2, NR), B, SH>>>(MSGV + c, 768, 3, W1_v, 128, MV + c, 384, 3, 256, rs256, INVD, 0, 0);
        mma_gemm_kernel<<<dim3(2, NR), B, SH>>>(UV + c, 384, 3, Wres_v, 128, MV + c, 384, 3, 128, rs128, nullptr, 1, 0);
    }
    act_kernel<<<NN * 128 / 256, B>>>();
    // f_s -> out[:, :, 0] ; f_v[c] -> out[:, :, 1+c]
    mma_gemm_kernel<<<dim3(2, NR), B, SH>>>(OS, 128, 1, W2_s, 128, out, 512, 4, 128, rs128, nullptr, 0, 0);
    for (int c = 0; c < 3; c++)
        mma_gemm_kernel<<<dim3(2, NR), B, SH>>>(OV + c, 384, 3, W2_v, 128, out + 1 + c, 512, 4, 128, rs128, nullptr, 0, 0);
}

// round 6
// speedup vs baseline: 1.6948x; 1.5644x over previous
#include <cuda_runtime.h>
#include <cuda_bf16.h>
#include <cstdint>

#define NN 8192
#define EE 131072
#define IS3 0.5773502691896258f

// ---------------- static scratch ----------------
__device__ float g_US[NN*128];
__device__ float g_UV[NN*384];
__device__ float g_ABCD[NN*256];          // AS|AT|BS|BT
__device__ float g_T08[(size_t)EE*128];   // T0|T0D
__device__ float g_TPW[(size_t)EE*512];
__device__ float g_ED[EE];
__device__ float g_MSGS[NN*256];          // pre-scaled by invd
__device__ float g_MSGV[NN*768];          // pre-scaled by invd
__device__ float g_MS[NN*256];
__device__ float g_MV[NN*384];
__device__ float g_OS[NN*128];
__device__ float g_OV[NN*384];
__device__ int   g_CNT[NN];
__device__ int   g_OFF[NN+1];
__device__ int   g_CUR[NN];
__device__ int   g_BKT[EE];
// packed weights
__device__ float g_Wns[128*256];          // [W_skip_s | W_up_s]
__device__ float g_Wnv[128*256];          // [W_skip_v | W_up_v]
__device__ float g_Wc[10*256];            // combined node_attrs->AS|AT|BS|BT (rs10 folded)
__device__ float g_Wt8[8*128];            // [W_r0[0:8] | W_d0[0:8]]
__device__ float g_Wms[384*256];          // [W1_s*rs256 ; Wres_s*rs128]
__device__ float g_Wmv[384*128];          // [W1_v*rs256 ; Wres_v*rs128]

#define RS128 0.08838834764831845f
#define RS10  0.31622776601683794f
#define RS64  0.125f
#define RS256 0.0625f
#define RS264 0.061545745489666336f

// ---------------- tf32 helpers ----------------
__device__ __forceinline__ uint32_t f2tf(float x) {
    uint32_t u;
    asm("cvt.rna.tf32.f32 %0, %1;" : "=r"(u) : "f"(x));
    return u;
}
__device__ __forceinline__ void mma_tf32(float* c, const uint32_t* a, uint32_t b0, uint32_t b1) {
    asm volatile(
        "mma.sync.aligned.m16n8k8.row.col.f32.tf32.tf32.f32 "
        "{%0,%1,%2,%3}, {%4,%5,%6,%7}, {%8,%9}, {%0,%1,%2,%3};"
        : "+f"(c[0]), "+f"(c[1]), "+f"(c[2]), "+f"(c[3])
        : "r"(a[0]), "r"(a[1]), "r"(a[2]), "r"(a[3]), "r"(b0), "r"(b1));
}
__device__ __forceinline__ float siluf(float x) { return x / (1.f + __expf(-x)); }

#define AP 68
#define BP 72
#define MMA_SMEM ((128*AP + 64*BP) * 4)
#define EDGE_SMEM (MMA_SMEM + 64*4 + 256*4)

// 128x64 tile MMA over one 64-deep K chunk in smem
__device__ __forceinline__ void tile_mma64(
    const uint32_t* __restrict__ As, const uint32_t* __restrict__ Bs,
    int wr, int wc, int g, int l, float acc[2][4][4])
{
    #pragma unroll
    for (int kt = 0; kt < 8; kt++) {
        uint32_t a[2][4];
        #pragma unroll
        for (int mt = 0; mt < 2; mt++) {
            int base = (wr * 32 + mt * 16 + g) * AP + kt * 8 + l;
            a[mt][0] = As[base];
            a[mt][1] = As[base + 8 * AP];
            a[mt][2] = As[base + 4];
            a[mt][3] = As[base + 8 * AP + 4];
        }
        #pragma unroll
        for (int nt = 0; nt < 4; nt++) {
            int bcol = wc * 32 + nt * 8 + g;
            uint32_t b0 = Bs[(kt * 8 + l) * BP + bcol];
            uint32_t b1 = Bs[(kt * 8 + l + 4) * BP + bcol];
            mma_tf32(acc[0][nt], a[0], b0, b1);
            mma_tf32(acc[1][nt], a[1], b0, b1);
        }
    }
}

// ---------------- unified strided/split GEMM ----------------
// Y[r,c] = scale * sum_k Xsel[r,k] * W[k,c]
// X region: k < K1 -> X1 (ldx1, sx1), else X2 at k-K1. blockIdx.z adds zx/zy element offsets.
// Y region: c < N1 -> Y1, else Y2 at c-N1.
__global__ void __launch_bounds__(256) mma_gemm_kernel(
    const float* __restrict__ X1, int ldx1, int sx1, int zx1,
    const float* __restrict__ X2, int ldx2, int sx2, int zx2, int K1,
    const float* __restrict__ W, int wld,
    float* __restrict__ Y1, int ldy1, int sy1, int zy1,
    float* __restrict__ Y2, int ldy2, int sy2, int zy2, int N1,
    int K, float scale)
{
    extern __shared__ uint32_t smem[];
    uint32_t* As = smem;
    uint32_t* Bs = smem + 128 * AP;

    int t  = threadIdx.x;
    int r0 = blockIdx.y * 128;
    int c0 = blockIdx.x * 64;
    int z  = blockIdx.z;

    int warp = t >> 5, lane = t & 31;
    int wr = warp >> 1, wc = warp & 1;
    int g = lane >> 2, l = lane & 3;

    float acc[2][4][4] = {};

    for (int k0 = 0; k0 < K; k0 += 64) {
        const float* Xp; int ld, sxx, kb;
        if (k0 < K1) { Xp = X1 + (size_t)z * zx1; ld = ldx1; sxx = sx1; kb = k0; }
        else         { Xp = X2 + (size_t)z * zx2; ld = ldx2; sxx = sx2; kb = k0 - K1; }
        int rem = K - k0;

        if (sxx == 1 && rem >= 64) {
            #pragma unroll
            for (int i = 0; i < 8; i++) {
                int e = t + i * 256;
                int row = e >> 4, c4 = (e & 15) * 4;
                float4 v = *reinterpret_cast<const float4*>(
                    &Xp[(size_t)(r0 + row) * ld + kb + c4]);
                uint4 u = make_uint4(f2tf(v.x), f2tf(v.y), f2tf(v.z), f2tf(v.w));
                *reinterpret_cast<uint4*>(&As[row * AP + c4]) = u;
            }
        } else {
            #pragma unroll
            for (int i = 0; i < 32; i++) {
                int e = t + i * 256;
                int row = e >> 6, col = e & 63;
                float x = (col < rem) ? Xp[(size_t)(r0 + row) * ld + (size_t)(kb + col) * sxx] : 0.f;
                As[row * AP + col] = f2tf(x);
            }
        }
        #pragma unroll
        for (int i = 0; i < 4; i++) {
            int e = t + i * 256;
            int row = e >> 4, c4 = (e & 15) * 4;
            int kk = k0 + row;
            float4 v = make_float4(0.f, 0.f, 0.f, 0.f);
            if (kk < K)
                v = *reinterpret_cast<const float4*>(&W[(size_t)kk * wld + c0 + c4]);
            uint4 u = make_uint4(f2tf(v.x), f2tf(v.y), f2tf(v.z), f2tf(v.w));
            *reinterpret_cast<uint4*>(&Bs[row * BP + c4]) = u;
        }
        __syncthreads();
        tile_mma64(As, Bs, wr, wc, g, l, acc);
        __syncthreads();
    }

    float* Yp; int ldy, syy; int colb;
    if (Y2 != nullptr && c0 >= N1) {
        Yp = Y2 + (size_t)z * zy2; ldy = ldy2; syy = sy2; colb = c0 - N1;
    } else {
        Yp = Y1 + (size_t)z * zy1; ldy = ldy1; syy = sy1; colb = c0;
    }

    #pragma unroll
    for (int mt = 0; mt < 2; mt++)
        #pragma unroll
        for (int idx = 0; idx < 4; idx++) {
            int row = r0 + wr * 32 + mt * 16 + g + ((idx >= 2) ? 8 : 0);
            #pragma unroll
            for (int nt = 0; nt < 4; nt++) {
                int col = colb + wc * 32 + nt * 8 + 2 * l + (idx & 1);
                Yp[(size_t)row * ldy + (size_t)col * syy] = acc[mt][nt][idx] * scale;
            }
        }
}

// ---------------- fused edge MLP: h0 assembly + silu, r1, r2, r3, density head ----------------
__global__ void __launch_bounds__(256) edge_mlp_kernel(
    const int* __restrict__ ei, const float* __restrict__ W_r1,
    const float* __restrict__ W_r2, const float* __restrict__ W_r3,
    const float* __restrict__ Wd1)
{
    extern __shared__ uint32_t smem[];
    uint32_t* As = smem;
    uint32_t* Bs = smem + 128 * AP;
    float* sWd1 = (float*)(Bs + 64 * BP);
    int* sSnd = (int*)(sWd1 + 64);
    int* sRcv = sSnd + 128;

    int t = threadIdx.x;
    int e0 = blockIdx.x * 128;
    int warp = t >> 5, lane = t & 31;
    int wr = warp >> 1, wc = warp & 1;
    int g = lane >> 2, l = lane & 3;

    if (t < 64) sWd1[t] = Wd1[t];
    if (t < 128) sSnd[t] = ei[e0 + t];
    else sRcv[t - 128] = ei[EE + e0 + t - 128];
    __syncthreads();

    // stage h0 = silu((T0 + AS[snd] + AT[rcv]) * rs264) into As
    #pragma unroll
    for (int i = 0; i < 32; i++) {
        int e = t + i * 256;
        int row = e >> 6, c = e & 63;
        int ed = e0 + row;
        float h0 = (g_T08[(size_t)ed * 128 + c]
                  + g_ABCD[(size_t)sSnd[row] * 256 + c]
                  + g_ABCD[(size_t)sRcv[row] * 256 + 64 + c]) * RS264;
        As[row * AP + c] = f2tf(siluf(h0));
    }
    // density head: warp w handles edges w, w+8, ...
    for (int el = warp; el < 128; el += 8) {
        int ed = e0 + el;
        int snd = sSnd[el], rcv = sRcv[el];
        float sum = 0.f;
        #pragma unroll
        for (int h = 0; h < 2; h++) {
            int c = lane + h * 32;
            float d0 = (g_T08[(size_t)ed * 128 + 64 + c]
                      + g_ABCD[(size_t)snd * 256 + 128 + c]
                      + g_ABCD[(size_t)rcv * 256 + 192 + c]) * RS264;
            sum += siluf(d0) * sWd1[c];
        }
        #pragma unroll
        for (int o = 16; o > 0; o >>= 1)
            sum += __shfl_down_sync(0xffffffff, sum, o);
        if (lane == 0) {
            float x = sum * RS64;
            g_ED[ed] = tanhf(x * x);
        }
    }
    // load W_r1
    #pragma unroll
    for (int i = 0; i < 4; i++) {
        int e = t + i * 256;
        int row = e >> 4, c4 = (e & 15) * 4;
        float4 v = *reinterpret_cast<const float4*>(&W_r1[row * 64 + c4]);
        uint4 u = make_uint4(f2tf(v.x), f2tf(v.y), f2tf(v.z), f2tf(v.w));
        *reinterpret_cast<uint4*>(&Bs[row * BP + c4]) = u;
    }
    __syncthreads();

    float acc[2][4][4] = {};
    tile_mma64(As, Bs, wr, wc, g, l, acc);
    __syncthreads();

    // h1 = silu(acc*rs64) -> As ; load W_r2
    #pragma unroll
    for (int mt = 0; mt < 2; mt++)
        #pragma unroll
        for (int idx = 0; idx < 4; idx++) {
            int row = wr * 32 + mt * 16 + g + ((idx >= 2) ? 8 : 0);
            #pragma unroll
            for (int nt = 0; nt < 4; nt++) {
                int col = wc * 32 + nt * 8 + 2 * l + (idx & 1);
                As[row * AP + col] = f2tf(siluf(acc[mt][nt][idx] * RS64));
            }
        }
    #pragma unroll
    for (int i = 0; i < 4; i++) {
        int e = t + i * 256;
        int row = e >> 4, c4 = (e & 15) * 4;
        float4 v = *reinterpret_cast<const float4*>(&W_r2[row * 64 + c4]);
        uint4 u = make_uint4(f2tf(v.x), f2tf(v.y), f2tf(v.z), f2tf(v.w));
        *reinterpret_cast<uint4*>(&Bs[row * BP + c4]) = u;
    }
    __syncthreads();

    float acc2[2][4][4] = {};
    tile_mma64(As, Bs, wr, wc, g, l, acc2);
    __syncthreads();

    // h2 = silu(acc2*rs64) -> As
    #pragma unroll
    for (int mt = 0; mt < 2; mt++)
        #pragma unroll
        for (int idx = 0; idx < 4; idx++) {
            int row = wr * 32 + mt * 16 + g + ((idx >= 2) ? 8 : 0);
            #pragma unroll
            for (int nt = 0; nt < 4; nt++) {
                int col = wc * 32 + nt * 8 + 2 * l + (idx & 1);
                As[row * AP + col] = f2tf(siluf(acc2[mt][nt][idx] * RS64));
            }
        }
    __syncthreads();

    // r3: 8 column tiles of 64
    for (int ct = 0; ct < 8; ct++) {
        #pragma unroll
        for (int i = 0; i < 4; i++) {
            int e = t + i * 256;
            int row = e >> 4, c4 = (e & 15) * 4;
            float4 v = *reinterpret_cast<const float4*>(&W_r3[row * 512 + ct * 64 + c4]);
            uint4 u = make_uint4(f2tf(v.x), f2tf(v.y), f2tf(v.z), f2tf(v.w));
            *reinterpret_cast<uint4*>(&Bs[row * BP + c4]) = u;
        }
        __syncthreads();
        float acc3[2][4][4] = {};
        tile_mma64(As, Bs, wr, wc, g, l, acc3);
        #pragma unroll
        for (int mt = 0; mt < 2; mt++)
            #pragma unroll
            for (int idx = 0; idx < 4; idx++) {
                int row = e0 + wr * 32 + mt * 16 + g + ((idx >= 2) ? 8 : 0);
                #pragma unroll
                for (int nt = 0; nt < 4; nt++) {
                    int col = ct * 64 + wc * 32 + nt * 8 + 2 * l + (idx & 1);
                    g_TPW[(size_t)row * 512 + col] = acc3[mt][nt][idx] * RS64;
                }
            }
        __syncthreads();
    }
}

// ---------------- weight prep ----------------
__global__ void __launch_bounds__(256) prep_kernel(
    const float* __restrict__ W_skip_s, const float* __restrict__ W_skip_v,
    const float* __restrict__ W_up_s,   const float* __restrict__ W_up_v,
    const float* __restrict__ W_src,    const float* __restrict__ W_tgt,
    const float* __restrict__ W_r0,     const float* __restrict__ W_d0,
    const float* __restrict__ W1_s,     const float* __restrict__ W1_v,
    const float* __restrict__ Wres_s,   const float* __restrict__ Wres_v)
{
    int id = blockIdx.x * 256 + threadIdx.x;
    if (id < 128 * 256) {
        int m = id >> 8, j = id & 255;
        g_Wns[id] = (j < 128) ? W_skip_s[m * 128 + j] : W_up_s[m * 128 + j - 128];
        g_Wnv[id] = (j < 128) ? W_skip_v[m * 128 + j] : W_up_v[m * 128 + j - 128];
    }
    if (id < 8 * 128) {
        int m = id >> 7, j = id & 127;
        g_Wt8[id] = (j < 64) ? W_r0[m * 64 + j] : W_d0[m * 64 + j - 64];
    }
    if (id < 384 * 256) {
        int k = id >> 8, j = id & 255;
        g_Wms[id] = (k < 256) ? W1_s[k * 256 + j] * RS256
                              : Wres_s[(k - 256) * 256 + j] * RS128;
    }
    if (id < 384 * 128) {
        int k = id / 128, j = id % 128;
        g_Wmv[id] = (k < 256) ? W1_v[k * 128 + j] * RS256
                              : Wres_v[(k - 256) * 128 + j] * RS128;
    }
    if (id < 10 * 256) {
        int a = id >> 8, j = id & 255;
        int q = j >> 6, jj = j & 63;
        const float* S = (q == 0 || q == 2) ? W_src : W_tgt;
        const float* M = (q < 2) ? W_r0 : W_d0;
        int off = (q == 0 || q == 2) ? 8 : 136;
        float s = 0.f;
        for (int m = 0; m < 128; m++)
            s += S[a * 128 + m] * M[(off + m) * 64 + jj];
        g_Wc[a * 256 + j] = s * RS10;
    }
}

// ---------------- bucketing ----------------
__global__ void zero_cnt_kernel() {
    int i = blockIdx.x * blockDim.x + threadIdx.x;
    if (i < NN) g_CNT[i] = 0;
}
__global__ void count_kernel(const int* __restrict__ ei) {
    int e = blockIdx.x * blockDim.x + threadIdx.x;
    if (e < EE) atomicAdd(&g_CNT[ei[EE + e]], 1);
}
__global__ void __launch_bounds__(1024) scan_kernel() {
    __shared__ int sums[1024];
    int t = threadIdx.x;
    int base = t * 8;
    int local[8];
    int s = 0;
    #pragma unroll
    for (int i = 0; i < 8; i++) { local[i] = g_CNT[base + i]; s += local[i]; }
    sums[t] = s;
    __syncthreads();
    for (int d = 1; d < 1024; d <<= 1) {
        int v = (t >= d) ? sums[t - d] : 0;
        __syncthreads();
        sums[t] += v;
        __syncthreads();
    }
    int run = (t == 0) ? 0 : sums[t - 1];
    #pragma unroll
    for (int i = 0; i < 8; i++) { g_OFF[base + i] = run; g_CUR[base + i] = run; run += local[i]; }
    if (t == 1023) g_OFF[NN] = run;
}
__global__ void fill_kernel(const int* __restrict__ ei) {
    int e = blockIdx.x * blockDim.x + threadIdx.x;
    if (e < EE) {
        int pos = atomicAdd(&g_CUR[ei[EE + e]], 1);
        g_BKT[pos] = e;
    }
}
__global__ void sort_kernel() {
    int n = blockIdx.x * blockDim.x + threadIdx.x;
    if (n >= NN) return;
    int s = g_OFF[n], t = g_OFF[n + 1];
    for (int i = s + 1; i < t; i++) {
        int v = g_BKT[i];
        int j = i - 1;
        while (j >= s && g_BKT[j] > v) { g_BKT[j + 1] = g_BKT[j]; j--; }
        g_BKT[j + 1] = v;
    }
}

// ---------------- per-node gather (segment sum + density + invd fold) ----------------
__global__ void __launch_bounds__(256) gather_kernel(
    const int* __restrict__ ei, const float* __restrict__ edge_attrs,
    const float* __restrict__ alpha, const float* __restrict__ beta)
{
    __shared__ float red[256];
    int n = blockIdx.x;
    int j = threadIdx.x;
    int s = g_OFF[n], t = g_OFF[n + 1];
    float as = 0.f, av0 = 0.f, av1 = 0.f, av2 = 0.f;

    for (int i = s; i < t; i++) {
        int e = g_BKT[i];
        int snd = ei[e];
        float y0  = __ldg(&edge_attrs[e * 4 + 0]);
        float y10 = __ldg(&edge_attrs[e * 4 + 1]);
        float y11 = __ldg(&edge_attrs[e * 4 + 2]);
        float y12 = __ldg(&edge_attrs[e * 4 + 3]);
        const float* tp = g_TPW + (size_t)e * 512;
        if (j < 128) {
            float w1 = tp[j], w2 = tp[128 + j];
            float xs = g_US[snd * 128 + j];
            as = fmaf(w1 * xs, y0, as);
            float t2 = w2 * xs * IS3;
            av0 = fmaf(t2, y10, av0);
            av1 = fmaf(t2, y11, av1);
            av2 = fmaf(t2, y12, av2);
        } else {
            int u = j - 128;
            float w3 = tp[256 + u], w4 = tp[384 + u];
            const float* xv = g_UV + snd * 384 + u * 3;
            float x0 = xv[0], x1 = xv[1], x2 = xv[2];
            float sv = x0 * y10 + x1 * y11 + x2 * y12;
            as = fmaf(w4 * IS3, sv, as);
            float t3 = w3 * y0 * IS3;
            av0 = fmaf(t3, x0, av0);
            av1 = fmaf(t3, x1, av1);
            av2 = fmaf(t3, x2, av2);
        }
    }
    // density reduction
    float dsum = 0.f;
    for (int i = s + j; i < t; i += 256) dsum += g_ED[g_BKT[i]];
    red[j] = dsum;
    __syncthreads();
    for (int o = 128; o > 0; o >>= 1) {
        if (j < o) red[j] += red[j + o];
        __syncthreads();
    }
    float invd = 1.f / (red[0] * beta[0] + alpha[0]);

    g_MSGS[n * 256 + j] = as * invd;
    g_MSGV[n * 768 + j * 3 + 0] = av0 * invd;
    g_MSGV[n * 768 + j * 3 + 1] = av1 * invd;
    g_MSGV[n * 768 + j * 3 + 2] = av2 * invd;
}

// out_s = silu(m_s[:,:128]); out_v = m_v * sigmoid(m_s[:,128:])
__global__ void act_kernel() {
    int idx = blockIdx.x * blockDim.x + threadIdx.x;
    int n = idx >> 7, u = idx & 127;
    float ms = g_MS[n * 256 + u];
    g_OS[n * 128 + u] = ms / (1.f + __expf(-ms));
    float sg = 1.f / (1.f + __expf(-g_MS[n * 256 + 128 + u]));
    int b = n * 384 + u * 3;
    g_OV[b + 0] = g_MV[b + 0] * sg;
    g_OV[b + 1] = g_MV[b + 1] * sg;
    g_OV[b + 2] = g_MV[b + 2] * sg;
}

// ---------------- host ----------------
static float* sym(const void* symbol) {
    void* p = nullptr;
    cudaGetSymbolAddress(&p, symbol);
    return (float*)p;
}

extern "C" void kernel_launch(void* const* d_in, const int* in_sizes, int n_in,
                              void* d_out, int out_size)
{
    const float* node_attrs = (const float*)d_in[0];
    const float* node_feats = (const float*)d_in[1];
    const float* edge_attrs = (const float*)d_in[2];
    const float* edge_feats = (const float*)d_in[3];
    const int*   ei         = (const int*)  d_in[4];
    const float* W_skip_s = (const float*)d_in[5];
    const float* W_skip_v = (const float*)d_in[6];
    const float* W_up_s   = (const float*)d_in[7];
    const float* W_up_v   = (const float*)d_in[8];
    const float* W_src    = (const float*)d_in[9];
    const float* W_tgt    = (const float*)d_in[10];
    const float* W_r0     = (const float*)d_in[11];
    const float* W_r1     = (const float*)d_in[12];
    const float* W_r2     = (const float*)d_in[13];
    const float* W_r3     = (const float*)d_in[14];
    const float* W_d0     = (const float*)d_in[15];
    const float* W_d1     = (const float*)d_in[16];
    const float* W1_s     = (const float*)d_in[17];
    const float* W1_v     = (const float*)d_in[18];
    const float* Wres_s   = (const float*)d_in[19];
    const float* Wres_v   = (const float*)d_in[20];
    const float* W2_s     = (const float*)d_in[21];
    const float* W2_v     = (const float*)d_in[22];
    const float* alpha    = (const float*)d_in[23];
    const float* beta     = (const float*)d_in[24];

    float* out    = (float*)d_out;                      // (N,128,4)
    float* out_sc = (float*)d_out + (size_t)NN * 512;   // (N,512)

    float* US   = sym(g_US);   float* UV   = sym(g_UV);
    float* ABCD = sym(g_ABCD); float* T08  = sym(g_T08);
    float* MSGS = sym(g_MSGS); float* MSGV = sym(g_MSGV);
    float* MS   = sym(g_MS);   float* MV   = sym(g_MV);
    float* OS   = sym(g_OS);   float* OV   = sym(g_OV);
    float* Wns  = sym(g_Wns);  float* Wnv  = sym(g_Wnv);
    float* Wc   = sym(g_Wc);   float* Wt8  = sym(g_Wt8);
    float* Wms  = sym(g_Wms);  float* Wmv  = sym(g_Wmv);

    cudaFuncSetAttribute(mma_gemm_kernel,
                         cudaFuncAttributeMaxDynamicSharedMemorySize, MMA_SMEM);
    cudaFuncSetAttribute(edge_mlp_kernel,
                         cudaFuncAttributeMaxDynamicSharedMemorySize, EDGE_SMEM);

    dim3 B(256);
    const int BIG = 1 << 30;

    // weight prep
    prep_kernel<<<384, B>>>(W_skip_s, W_skip_v, W_up_s, W_up_v, W_src, W_tgt,
                            W_r0, W_d0, W1_s, W1_v, Wres_s, Wres_v);

    // bucketing
    zero_cnt_kernel<<<NN / 256, B>>>();
    count_kernel<<<EE / 256, B>>>(ei);
    scan_kernel<<<1, 1024>>>();
    fill_kernel<<<EE / 256, B>>>(ei);
    sort_kernel<<<NN / 256, B>>>();

    // node precompute: s-path -> [sc_s | US]
    mma_gemm_kernel<<<dim3(4, 64), B, MMA_SMEM>>>(
        node_feats, 512, 1, 0, nullptr, 0, 0, 0, BIG,
        Wns, 256, out_sc, 512, 1, 0, US, 128, 1, 0, 128, 128, RS128);
    // v-path (z=3) -> [sc_v | UV]
    mma_gemm_kernel<<<dim3(4, 64, 3), B, MMA_SMEM>>>(
        node_feats + 128, 512, 3, 1, nullptr, 0, 0, 0, BIG,
        Wnv, 256, out_sc + 128, 512, 3, 1, UV, 384, 3, 1, 128, 128, RS128);
    // node_attrs -> ABCD (K=10, combined weights)
    mma_gemm_kernel<<<dim3(4, 64), B, MMA_SMEM>>>(
        node_attrs, 10, 1, 0, nullptr, 0, 0, 0, BIG,
        Wc, 256, ABCD, 256, 1, 0, nullptr, 0, 0, 0, BIG, 10, 1.f);
    // edge_feats -> T08 (K=8)
    mma_gemm_kernel<<<dim3(2, 1024), B, MMA_SMEM>>>(
        edge_feats, 8, 1, 0, nullptr, 0, 0, 0, BIG,
        Wt8, 128, T08, 128, 1, 0, nullptr, 0, 0, 0, BIG, 8, 1.f);

    // fused edge MLP -> TPW, ED
    edge_mlp_kernel<<<EE / 128, B, EDGE_SMEM>>>(ei, W_r1, W_r2, W_r3, W_d1);

    // message aggregation (invd folded)
    gather_kernel<<<NN, B>>>(ei, edge_attrs, alpha, beta);

    // MS = [MSGS | US] @ Wms
    mma_gemm_kernel<<<dim3(4, 64), B, MMA_SMEM>>>(
        MSGS, 256, 1, 0, US, 128, 1, 0, 256,
        Wms, 256, MS, 256, 1, 0, nullptr, 0, 0, 0, BIG, 384, 1.f);
    // MV = [MSGV | UV] @ Wmv (z=3)
    mma_gemm_kernel<<<dim3(2, 64, 3), B, MMA_SMEM>>>(
        MSGV, 768, 3, 1, UV, 384, 3, 1, 256,
        Wmv, 128, MV, 384, 3, 1, nullptr, 0, 0, 0, BIG, 384, 1.f);

    act_kernel<<<NN * 128 / 256, B>>>();

    // f_s -> out[:,:,0]
    mma_gemm_kernel<<<dim3(2, 64), B, MMA_SMEM>>>(
        OS, 128, 1, 0, nullptr, 0, 0, 0, BIG,
        W2_s, 128, out, 512, 4, 0, nullptr, 0, 0, 0, BIG, 128, RS128);
    // f_v -> out[:,:,1+c] (z=3)
    mma_gemm_kernel<<<dim3(2, 64, 3), B, MMA_SMEM>>>(
        OV, 384, 3, 1, nullptr, 0, 0, 0, BIG,
        W2_v, 128, out + 1, 512, 4, 1, nullptr, 0, 0, 0, BIG, 128, RS128);
}

// round 8
// speedup vs baseline: 2.0888x; 1.2325x over previous
#include <cuda_runtime.h>
#include <cuda_bf16.h>
#include <cuda_fp16.h>
#include <cstdint>

#define NN 8192
#define EE 131072
#define IS3 0.5773502691896258f

// ---------------- static scratch ----------------
__device__ float g_US[NN*128];
__device__ float g_UV[NN*384];
__device__ float g_ABCD[NN*256];          // AS|AT|BS|BT
__device__ __half g_TPWh[(size_t)EE*512]; // position-ordered, fp16
__device__ float g_ED[EE];                // position-ordered
__device__ int   g_PSND[EE];              // position-ordered sender
__device__ float4 g_PEA[EE];              // position-ordered edge_attrs
__device__ float g_PEF[(size_t)EE*8];     // position-ordered edge_feats
__device__ float g_MSGS[NN*256];
__device__ float g_MSGV[NN*768];
__device__ float g_MS[NN*256];
__device__ float g_MV[NN*384];
__device__ float g_OS[NN*128];
__device__ float g_OV[NN*384];
__device__ int   g_CNT[NN];
__device__ int   g_OFF[NN+1];
__device__ int   g_CUR[NN];
__device__ int   g_BKT[EE];
// packed weights
__device__ float g_Wns[128*256];
__device__ float g_Wnv[128*256];
__device__ float g_Wc[10*256];
__device__ float g_Wt8[8*128];
__device__ float g_Wms[384*256];
__device__ float g_Wmv[384*128];

#define RS128 0.08838834764831845f
#define RS10  0.31622776601683794f
#define RS64  0.125f
#define RS256 0.0625f
#define RS264 0.061545745489666336f

// ---------------- tf32 helpers ----------------
__device__ __forceinline__ uint32_t f2tf(float x) {
    uint32_t u;
    asm("cvt.rna.tf32.f32 %0, %1;" : "=r"(u) : "f"(x));
    return u;
}
__device__ __forceinline__ void mma_tf32(float* c, const uint32_t* a, uint32_t b0, uint32_t b1) {
    asm volatile(
        "mma.sync.aligned.m16n8k8.row.col.f32.tf32.tf32.f32 "
        "{%0,%1,%2,%3}, {%4,%5,%6,%7}, {%8,%9}, {%0,%1,%2,%3};"
        : "+f"(c[0]), "+f"(c[1]), "+f"(c[2]), "+f"(c[3])
        : "r"(a[0]), "r"(a[1]), "r"(a[2]), "r"(a[3]), "r"(b0), "r"(b1));
}
__device__ __forceinline__ float siluf(float x) { return x / (1.f + __expf(-x)); }

#define AP 68
#define BP 72
#define MMA_SMEM ((128*AP + 64*BP) * 4)
#define EDGE_SMEM (MMA_SMEM + (64 + 384 + 1024 + 1024) * 4)

__device__ __forceinline__ void tile_mma64(
    const uint32_t* __restrict__ As, const uint32_t* __restrict__ Bs,
    int wr, int wc, int g, int l, float acc[2][4][4])
{
    #pragma unroll
    for (int kt = 0; kt < 8; kt++) {
        uint32_t a[2][4];
        #pragma unroll
        for (int mt = 0; mt < 2; mt++) {
            int base = (wr * 32 + mt * 16 + g) * AP + kt * 8 + l;
            a[mt][0] = As[base];
            a[mt][1] = As[base + 8 * AP];
            a[mt][2] = As[base + 4];
            a[mt][3] = As[base + 8 * AP + 4];
        }
        #pragma unroll
        for (int nt = 0; nt < 4; nt++) {
            int bcol = wc * 32 + nt * 8 + g;
            uint32_t b0 = Bs[(kt * 8 + l) * BP + bcol];
            uint32_t b1 = Bs[(kt * 8 + l + 4) * BP + bcol];
            mma_tf32(acc[0][nt], a[0], b0, b1);
            mma_tf32(acc[1][nt], a[1], b0, b1);
        }
    }
}

// ---------------- unified strided/split GEMM ----------------
__global__ void __launch_bounds__(256) mma_gemm_kernel(
    const float* __restrict__ X1, int ldx1, int sx1, int zx1,
    const float* __restrict__ X2, int ldx2, int sx2, int zx2, int K1,
    const float* __restrict__ W, int wld,
    float* __restrict__ Y1, int ldy1, int sy1, int zy1,
    float* __restrict__ Y2, int ldy2, int sy2, int zy2, int N1,
    int K, float scale)
{
    extern __shared__ uint32_t smem[];
    uint32_t* As = smem;
    uint32_t* Bs = smem + 128 * AP;

    int t  = threadIdx.x;
    int r0 = blockIdx.y * 128;
    int c0 = blockIdx.x * 64;
    int z  = blockIdx.z;

    int warp = t >> 5, lane = t & 31;
    int wr = warp >> 1, wc = warp & 1;
    int g = lane >> 2, l = lane & 3;

    float acc[2][4][4] = {};

    for (int k0 = 0; k0 < K; k0 += 64) {
        const float* Xp; int ld, sxx, kb;
        if (k0 < K1) { Xp = X1 + (size_t)z * zx1; ld = ldx1; sxx = sx1; kb = k0; }
        else         { Xp = X2 + (size_t)z * zx2; ld = ldx2; sxx = sx2; kb = k0 - K1; }
        int rem = K - k0;

        if (sxx == 1 && rem >= 64) {
            #pragma unroll
            for (int i = 0; i < 8; i++) {
                int e = t + i * 256;
                int row = e >> 4, c4 = (e & 15) * 4;
                float4 v = *reinterpret_cast<const float4*>(
                    &Xp[(size_t)(r0 + row) * ld + kb + c4]);
                uint4 u = make_uint4(f2tf(v.x), f2tf(v.y), f2tf(v.z), f2tf(v.w));
                *reinterpret_cast<uint4*>(&As[row * AP + c4]) = u;
            }
        } else {
            #pragma unroll
            for (int i = 0; i < 32; i++) {
                int e = t + i * 256;
                int row = e >> 6, col = e & 63;
                float x = (col < rem) ? Xp[(size_t)(r0 + row) * ld + (size_t)(kb + col) * sxx] : 0.f;
                As[row * AP + col] = f2tf(x);
            }
        }
        #pragma unroll
        for (int i = 0; i < 4; i++) {
            int e = t + i * 256;
            int row = e >> 4, c4 = (e & 15) * 4;
            int kk = k0 + row;
            float4 v = make_float4(0.f, 0.f, 0.f, 0.f);
            if (kk < K)
                v = *reinterpret_cast<const float4*>(&W[(size_t)kk * wld + c0 + c4]);
            uint4 u = make_uint4(f2tf(v.x), f2tf(v.y), f2tf(v.z), f2tf(v.w));
            *reinterpret_cast<uint4*>(&Bs[row * BP + c4]) = u;
        }
        __syncthreads();
        tile_mma64(As, Bs, wr, wc, g, l, acc);
        __syncthreads();
    }

    float* Yp; int ldy, syy; int colb;
    if (Y2 != nullptr && c0 >= N1) {
        Yp = Y2 + (size_t)z * zy2; ldy = ldy2; syy = sy2; colb = c0 - N1;
    } else {
        Yp = Y1 + (size_t)z * zy1; ldy = ldy1; syy = sy1; colb = c0;
    }

    #pragma unroll
    for (int mt = 0; mt < 2; mt++)
        #pragma unroll
        for (int idx = 0; idx < 4; idx++) {
            int row = r0 + wr * 32 + mt * 16 + g + ((idx >= 2) ? 8 : 0);
            #pragma unroll
            for (int nt = 0; nt < 4; nt++) {
                int col = colb + wc * 32 + nt * 8 + 2 * l + (idx & 1);
                Yp[(size_t)row * ldy + (size_t)col * syy] = acc[mt][nt][idx] * scale;
            }
        }
}

// ---------------- fused edge MLP (bucket-position order) ----------------
__global__ void __launch_bounds__(256) edge_mlp_kernel(
    const int* __restrict__ ei, const float* __restrict__ edge_attrs,
    const float* __restrict__ W_r1, const float* __restrict__ W_r2,
    const float* __restrict__ W_r3, const float* __restrict__ Wd1)
{
    extern __shared__ uint32_t smem[];
    uint32_t* As = smem;
    uint32_t* Bs = smem + 128 * AP;
    float* sWd1 = (float*)(Bs + 64 * BP);
    int*   sSnd = (int*)(sWd1 + 64);
    int*   sRcv = sSnd + 128;
    int*   sEd  = sRcv + 128;
    float* sEf  = (float*)(sEd + 128);       // [128][8]
    float* sW8  = sEf + 128 * 8;             // [8][128]

    int t = threadIdx.x;
    int e0 = blockIdx.x * 128;               // position base
    int warp = t >> 5, lane = t & 31;
    int wr = warp >> 1, wc = warp & 1;
    int g = lane >> 2, l = lane & 3;

    if (t < 64) sWd1[t] = Wd1[t];
    if (t < 128) {
        int ed = g_BKT[e0 + t];
        sEd[t] = ed;
        int snd = ei[ed];
        sSnd[t] = snd;
        sRcv[t] = ei[EE + ed];
        g_PSND[e0 + t] = snd;
        g_PEA[e0 + t] = reinterpret_cast<const float4*>(edge_attrs)[ed];
    }
    #pragma unroll
    for (int i = 0; i < 4; i++) sW8[t + i * 256] = g_Wt8[t + i * 256];
    // edge_feats rows (position order, staged by permute kernel): 256 float4s
    {
        float4 v = reinterpret_cast<const float4*>(g_PEF)[(size_t)e0 * 2 + t];
        reinterpret_cast<float4*>(sEf)[t] = v;
    }
    __syncthreads();

    // h0 = silu((ef8@W8[:, :64] + AS[snd] + AT[rcv]) * rs264) -> As
    #pragma unroll
    for (int i = 0; i < 32; i++) {
        int e = t + i * 256;
        int row = e >> 6, c = e & 63;
        float accv = 0.f;
        #pragma unroll
        for (int k = 0; k < 8; k++)
            accv = fmaf(sEf[row * 8 + k], sW8[k * 128 + c], accv);
        float h0 = (accv
                  + g_ABCD[(size_t)sSnd[row] * 256 + c]
                  + g_ABCD[(size_t)sRcv[row] * 256 + 64 + c]) * RS264;
        As[row * AP + c] = f2tf(siluf(h0));
    }
    // density head (cols 64..127 of packed W8)
    for (int el = warp; el < 128; el += 8) {
        int snd = sSnd[el], rcv = sRcv[el];
        float sum = 0.f;
        #pragma unroll
        for (int h = 0; h < 2; h++) {
            int c = lane + h * 32;
            float accv = 0.f;
            #pragma unroll
            for (int k = 0; k < 8; k++)
                accv = fmaf(sEf[el * 8 + k], sW8[k * 128 + 64 + c], accv);
            float d0 = (accv
                      + g_ABCD[(size_t)snd * 256 + 128 + c]
                      + g_ABCD[(size_t)rcv * 256 + 192 + c]) * RS264;
            sum += siluf(d0) * sWd1[c];
        }
        #pragma unroll
        for (int o = 16; o > 0; o >>= 1)
            sum += __shfl_down_sync(0xffffffff, sum, o);
        if (lane == 0) {
            float x = sum * RS64;
            g_ED[e0 + el] = tanhf(x * x);
        }
    }
    // W_r1
    #pragma unroll
    for (int i = 0; i < 4; i++) {
        int e = t + i * 256;
        int row = e >> 4, c4 = (e & 15) * 4;
        float4 v = *reinterpret_cast<const float4*>(&W_r1[row * 64 + c4]);
        uint4 u = make_uint4(f2tf(v.x), f2tf(v.y), f2tf(v.z), f2tf(v.w));
        *reinterpret_cast<uint4*>(&Bs[row * BP + c4]) = u;
    }
    __syncthreads();

    float acc[2][4][4] = {};
    tile_mma64(As, Bs, wr, wc, g, l, acc);
    __syncthreads();

    #pragma unroll
    for (int mt = 0; mt < 2; mt++)
        #pragma unroll
        for (int idx = 0; idx < 4; idx++) {
            int row = wr * 32 + mt * 16 + g + ((idx >= 2) ? 8 : 0);
            #pragma unroll
            for (int nt = 0; nt < 4; nt++) {
                int col = wc * 32 + nt * 8 + 2 * l + (idx & 1);
                As[row * AP + col] = f2tf(siluf(acc[mt][nt][idx] * RS64));
            }
        }
    #pragma unroll
    for (int i = 0; i < 4; i++) {
        int e = t + i * 256;
        int row = e >> 4, c4 = (e & 15) * 4;
        float4 v = *reinterpret_cast<const float4*>(&W_r2[row * 64 + c4]);
        uint4 u = make_uint4(f2tf(v.x), f2tf(v.y), f2tf(v.z), f2tf(v.w));
        *reinterpret_cast<uint4*>(&Bs[row * BP + c4]) = u;
    }
    __syncthreads();

    float acc2[2][4][4] = {};
    tile_mma64(As, Bs, wr, wc, g, l, acc2);
    __syncthreads();

    #pragma unroll
    for (int mt = 0; mt < 2; mt++)
        #pragma unroll
        for (int idx = 0; idx < 4; idx++) {
            int row = wr * 32 + mt * 16 + g + ((idx >= 2) ? 8 : 0);
            #pragma unroll
            for (int nt = 0; nt < 4; nt++) {
                int col = wc * 32 + nt * 8 + 2 * l + (idx & 1);
                As[row * AP + col] = f2tf(siluf(acc2[mt][nt][idx] * RS64));
            }
        }
    __syncthreads();

    for (int ct = 0; ct < 8; ct++) {
        #pragma unroll
        for (int i = 0; i < 4; i++) {
            int e = t + i * 256;
            int row = e >> 4, c4 = (e & 15) * 4;
            float4 v = *reinterpret_cast<const float4*>(&W_r3[row * 512 + ct * 64 + c4]);
            uint4 u = make_uint4(f2tf(v.x), f2tf(v.y), f2tf(v.z), f2tf(v.w));
            *reinterpret_cast<uint4*>(&Bs[row * BP + c4]) = u;
        }
        __syncthreads();
        float acc3[2][4][4] = {};
        tile_mma64(As, Bs, wr, wc, g, l, acc3);
        #pragma unroll
        for (int mt = 0; mt < 2; mt++)
            #pragma unroll
            for (int hi = 0; hi < 2; hi++) {
                int row = e0 + wr * 32 + mt * 16 + g + (hi ? 8 : 0);
                #pragma unroll
                for (int nt = 0; nt < 4; nt++) {
                    int col = ct * 64 + wc * 32 + nt * 8 + 2 * l;
                    __half2 h = __floats2half2_rn(acc3[mt][nt][hi * 2] * RS64,
                                                  acc3[mt][nt][hi * 2 + 1] * RS64);
                    *reinterpret_cast<__half2*>(&g_TPWh[(size_t)row * 512 + col]) = h;
                }
            }
        __syncthreads();
    }
}

// ---------------- weight prep ----------------
__global__ void __launch_bounds__(256) prep_kernel(
    const float* __restrict__ W_skip_s, const float* __restrict__ W_skip_v,
    const float* __restrict__ W_up_s,   const float* __restrict__ W_up_v,
    const float* __restrict__ W_src,    const float* __restrict__ W_tgt,
    const float* __restrict__ W_r0,     const float* __restrict__ W_d0,
    const float* __restrict__ W1_s,     const float* __restrict__ W1_v,
    const float* __restrict__ Wres_s,   const float* __restrict__ Wres_v)
{
    int id = blockIdx.x * 256 + threadIdx.x;
    if (id < 128 * 256) {
        int m = id >> 8, j = id & 255;
        g_Wns[id] = (j < 128) ? W_skip_s[m * 128 + j] : W_up_s[m * 128 + j - 128];
        g_Wnv[id] = (j < 128) ? W_skip_v[m * 128 + j] : W_up_v[m * 128 + j - 128];
    }
    if (id < 8 * 128) {
        int m = id >> 7, j = id & 127;
        g_Wt8[id] = (j < 64) ? W_r0[m * 64 + j] : W_d0[m * 64 + j - 64];
    }
    if (id < 384 * 256) {
        int k = id >> 8, j = id & 255;
        g_Wms[id] = (k < 256) ? W1_s[k * 256 + j] * RS256
                              : Wres_s[(k - 256) * 256 + j] * RS128;
    }
    if (id < 384 * 128) {
        int k = id / 128, j = id % 128;
        g_Wmv[id] = (k < 256) ? W1_v[k * 128 + j] * RS256
                              : Wres_v[(k - 256) * 128 + j] * RS128;
    }
    if (id < 10 * 256) {
        int a = id >> 8, j = id & 255;
        int q = j >> 6, jj = j & 63;
        const float* S = (q == 0 || q == 2) ? W_src : W_tgt;
        const float* M = (q < 2) ? W_r0 : W_d0;
        int off = (q == 0 || q == 2) ? 8 : 136;
        float s = 0.f;
        for (int m = 0; m < 128; m++)
            s += S[a * 128 + m] * M[(off + m) * 64 + jj];
        g_Wc[a * 256 + j] = s * RS10;
    }
}

// ---------------- bucketing ----------------
__global__ void zero_cnt_kernel() {
    int i = blockIdx.x * blockDim.x + threadIdx.x;
    if (i < NN) g_CNT[i] = 0;
}
__global__ void count_kernel(const int* __restrict__ ei) {
    int e = blockIdx.x * blockDim.x + threadIdx.x;
    if (e < EE) atomicAdd(&g_CNT[ei[EE + e]], 1);
}
__global__ void __launch_bounds__(1024) scan_kernel() {
    __shared__ int wt[32];
    int t = threadIdx.x, lane = t & 31, w = t >> 5;
    int base = t * 8;
    int local[8];
    int s = 0;
    #pragma unroll
    for (int i = 0; i < 8; i++) { local[i] = g_CNT[base + i]; s += local[i]; }
    int v = s;
    #pragma unroll
    for (int o = 1; o < 32; o <<= 1) {
        int u = __shfl_up_sync(0xffffffff, v, o);
        if (lane >= o) v += u;
    }
    if (lane == 31) wt[w] = v;
    __syncthreads();
    if (w == 0) {
        int x = wt[lane];
        #pragma unroll
        for (int o = 1; o < 32; o <<= 1) {
            int u = __shfl_up_sync(0xffffffff, x, o);
            if (lane >= o) x += u;
        }
        wt[lane] = x;
    }
    __syncthreads();
    int run = v - s + (w > 0 ? wt[w - 1] : 0);
    #pragma unroll
    for (int i = 0; i < 8; i++) { g_OFF[base + i] = run; g_CUR[base + i] = run; run += local[i]; }
    if (t == 1023) g_OFF[NN] = run;
}
__global__ void fill_kernel(const int* __restrict__ ei) {
    int e = blockIdx.x * blockDim.x + threadIdx.x;
    if (e < EE) {
        int pos = atomicAdd(&g_CUR[ei[EE + e]], 1);
        g_BKT[pos] = e;
    }
}
__global__ void sort_kernel() {
    int n = blockIdx.x * blockDim.x + threadIdx.x;
    if (n >= NN) return;
    int s = g_OFF[n], t = g_OFF[n + 1];
    for (int i = s + 1; i < t; i++) {
        int v = g_BKT[i];
        int j = i - 1;
        while (j >= s && g_BKT[j] > v) { g_BKT[j + 1] = g_BKT[j]; j--; }
        g_BKT[j + 1] = v;
    }
}
__global__ void permute_ef_kernel(const float* __restrict__ edge_feats) {
    int p = blockIdx.x * blockDim.x + threadIdx.x;
    if (p < EE * 2) {
        int pos = p >> 1, half = p & 1;
        int ed = g_BKT[pos];
        reinterpret_cast<float4*>(g_PEF)[(size_t)pos * 2 + half] =
            reinterpret_cast<const float4*>(edge_feats)[(size_t)ed * 2 + half];
    }
}

// ---------------- per-node gather (fully streaming) ----------------
__global__ void __launch_bounds__(256) gather_kernel(
    const float* __restrict__ alpha, const float* __restrict__ beta)
{
    __shared__ float red[256];
    int n = blockIdx.x;
    int j = threadIdx.x;
    int s = g_OFF[n], t = g_OFF[n + 1];
    float as = 0.f, av0 = 0.f, av1 = 0.f, av2 = 0.f;

    for (int i = s; i < t; i++) {
        int snd = g_PSND[i];
        float4 y = g_PEA[i];
        const __half* tp = g_TPWh + (size_t)i * 512;
        if (j < 128) {
            float w1 = __half2float(tp[j]);
            float w2 = __half2float(tp[128 + j]);
            float xs = g_US[snd * 128 + j];
            as = fmaf(w1 * xs, y.x, as);
            float t2 = w2 * xs * IS3;
            av0 = fmaf(t2, y.y, av0);
            av1 = fmaf(t2, y.z, av1);
            av2 = fmaf(t2, y.w, av2);
        } else {
            int u = j - 128;
            float w3 = __half2float(tp[256 + u]);
            float w4 = __half2float(tp[384 + u]);
            const float* xv = g_UV + snd * 384 + u * 3;
            float x0 = xv[0], x1 = xv[1], x2 = xv[2];
            float sv = x0 * y.y + x1 * y.z + x2 * y.w;
            as = fmaf(w4 * IS3, sv, as);
            float t3 = w3 * y.x * IS3;
            av0 = fmaf(t3, x0, av0);
            av1 = fmaf(t3, x1, av1);
            av2 = fmaf(t3, x2, av2);
        }
    }
    float dsum = 0.f;
    for (int i = s + j; i < t; i += 256) dsum += g_ED[i];
    red[j] = dsum;
    __syncthreads();
    for (int o = 128; o > 0; o >>= 1) {
        if (j < o) red[j] += red[j + o];
        __syncthreads();
    }
    float invd = 1.f / (red[0] * beta[0] + alpha[0]);

    g_MSGS[n * 256 + j] = as * invd;
    g_MSGV[n * 768 + j * 3 + 0] = av0 * invd;
    g_MSGV[n * 768 + j * 3 + 1] = av1 * invd;
    g_MSGV[n * 768 + j * 3 + 2] = av2 * invd;
}

__global__ void act_kernel() {
    int idx = blockIdx.x * blockDim.x + threadIdx.x;
    int n = idx >> 7, u = idx & 127;
    float ms = g_MS[n * 256 + u];
    g_OS[n * 128 + u] = ms / (1.f + __expf(-ms));
    float sg = 1.f / (1.f + __expf(-g_MS[n * 256 + 128 + u]));
    int b = n * 384 + u * 3;
    g_OV[b + 0] = g_MV[b + 0] * sg;
    g_OV[b + 1] = g_MV[b + 1] * sg;
    g_OV[b + 2] = g_MV[b + 2] * sg;
}

// ---------------- host ----------------
static float* sym(const void* symbol) {
    void* p = nullptr;
    cudaGetSymbolAddress(&p, symbol);
    return (float*)p;
}

extern "C" void kernel_launch(void* const* d_in, const int* in_sizes, int n_in,
                              void* d_out, int out_size)
{
    const float* node_attrs = (const float*)d_in[0];
    const float* node_feats = (const float*)d_in[1];
    const float* edge_attrs = (const float*)d_in[2];
    const float* edge_feats = (const float*)d_in[3];
    const int*   ei         = (const int*)  d_in[4];
    const float* W_skip_s = (const float*)d_in[5];
    const float* W_skip_v = (const float*)d_in[6];
    const float* W_up_s   = (const float*)d_in[7];
    const float* W_up_v   = (const float*)d_in[8];
    const float* W_src    = (const float*)d_in[9];
    const float* W_tgt    = (const float*)d_in[10];
    const float* W_r0     = (const float*)d_in[11];
    const float* W_r1     = (const float*)d_in[12];
    const float* W_r2     = (const float*)d_in[13];
    const float* W_r3     = (const float*)d_in[14];
    const float* W_d0     = (const float*)d_in[15];
    const float* W_d1     = (const float*)d_in[16];
    const float* W1_s     = (const float*)d_in[17];
    const float* W1_v     = (const float*)d_in[18];
    const float* Wres_s   = (const float*)d_in[19];
    const float* Wres_v   = (const float*)d_in[20];
    const float* W2_s     = (const float*)d_in[21];
    const float* W2_v     = (const float*)d_in[22];
    const float* alpha    = (const float*)d_in[23];
    const float* beta     = (const float*)d_in[24];

    float* out    = (float*)d_out;
    float* out_sc = (float*)d_out + (size_t)NN * 512;

    float* US   = sym(g_US);   float* UV   = sym(g_UV);
    float* ABCD = sym(g_ABCD);
    float* MSGS = sym(g_MSGS); float* MSGV = sym(g_MSGV);
    float* MS   = sym(g_MS);   float* MV   = sym(g_MV);
    float* OS   = sym(g_OS);   float* OV   = sym(g_OV);
    float* Wns  = sym(g_Wns);  float* Wnv  = sym(g_Wnv);
    float* Wc   = sym(g_Wc);
    float* Wms  = sym(g_Wms);  float* Wmv  = sym(g_Wmv);

    cudaFuncSetAttribute(mma_gemm_kernel,
                         cudaFuncAttributeMaxDynamicSharedMemorySize, MMA_SMEM);
    cudaFuncSetAttribute(edge_mlp_kernel,
                         cudaFuncAttributeMaxDynamicSharedMemorySize, EDGE_SMEM);

    dim3 B(256);
    const int BIG = 1 << 30;

    prep_kernel<<<384, B>>>(W_skip_s, W_skip_v, W_up_s, W_up_v, W_src, W_tgt,
                            W_r0, W_d0, W1_s, W1_v, Wres_s, Wres_v);

    zero_cnt_kernel<<<NN / 256, B>>>();
    count_kernel<<<EE / 256, B>>>(ei);
    scan_kernel<<<1, 1024>>>();
    fill_kernel<<<EE / 256, B>>>(ei);
    sort_kernel<<<NN / 256, B>>>();
    permute_ef_kernel<<<EE * 2 / 256, B>>>(edge_feats);

    mma_gemm_kernel<<<dim3(4, 64), B, MMA_SMEM>>>(
        node_feats, 512, 1, 0, nullptr, 0, 0, 0, BIG,
        Wns, 256, out_sc, 512, 1, 0, US, 128, 1, 0, 128, 128, RS128);
    mma_gemm_kernel<<<dim3(4, 64, 3), B, MMA_SMEM>>>(
        node_feats + 128, 512, 3, 1, nullptr, 0, 0, 0, BIG,
        Wnv, 256, out_sc + 128, 512, 3, 1, UV, 384, 3, 1, 128, 128, RS128);
    mma_gemm_kernel<<<dim3(4, 64), B, MMA_SMEM>>>(
        node_attrs, 10, 1, 0, nullptr, 0, 0, 0, BIG,
        Wc, 256, ABCD, 256, 1, 0, nullptr, 0, 0, 0, BIG, 10, 1.f);

    edge_mlp_kernel<<<EE / 128, B, EDGE_SMEM>>>(ei, edge_attrs, W_r1, W_r2, W_r3, W_d1);

    gather_kernel<<<NN, B>>>(alpha, beta);

    mma_gemm_kernel<<<dim3(4, 64), B, MMA_SMEM>>>(
        MSGS, 256, 1, 0, US, 128, 1, 0, 256,
        Wms, 256, MS, 256, 1, 0, nullptr, 0, 0, 0, BIG, 384, 1.f);
    mma_gemm_kernel<<<dim3(2, 64, 3), B, MMA_SMEM>>>(
        MSGV, 768, 3, 1, UV, 384, 3, 1, 256,
        Wmv, 128, MV, 384, 3, 1, nullptr, 0, 0, 0, BIG, 384, 1.f);

    act_kernel<<<NN * 128 / 256, B>>>();

    mma_gemm_kernel<<<dim3(2, 64), B, MMA_SMEM>>>(
        OS, 128, 1, 0, nullptr, 0, 0, 0, BIG,
        W2_s, 128, out, 512, 4, 0, nullptr, 0, 0, 0, BIG, 128, RS128);
    mma_gemm_kernel<<<dim3(2, 64, 3), B, MMA_SMEM>>>(
        OV, 384, 3, 1, nullptr, 0, 0, 0, BIG,
        W2_v, 128, out + 1, 512, 4, 1, nullptr, 0, 0, 0, BIG, 128, RS128);
}